// round 11
// baseline (speedup 1.0000x reference)
#include <cuda_runtime.h>

// ---------------- problem sizes ----------------
#define NC 100000
#define NT 300000
#define NP 50000
#define EM 300000
#define EI 600000
#define ET (EM + EI)
#define NOUT 10

#define NCTA 444          // 3 CTAs/SM on 148 SMs (GB300 has 152 -> co-residency guaranteed)
#define NTHR 256

// ---------------- scratch layout ----------------
#define OFF_MCS   0                               // [NC*8] sum x_t over c's transactions
#define OFF_MPS   (OFF_MCS + (size_t)NC * 8)      // [NP*8] sum x_t over p's transactions
#define OFF_CMC   (OFF_MPS + (size_t)NP * 8)      // [NC] deg(c)
#define OFF_CIP   (OFF_CMC + NC)                  // [NP] deg(p)
#define OFF_MTC   (OFF_CIP + NP)                  // [NT*8] sum x_c over t's customers
#define OFF_MTP   (OFF_MTC + (size_t)NT * 8)      // [NT*8] sum x_p over t's products
#define OFF_CMT   (OFF_MTP + (size_t)NT * 8)      // [NT] deg(t, makes)
#define OFF_CIT   (OFF_CMT + NT)                  // [NT] deg(t, in)
#define OFF_MMC   (OFF_CIT + NT)                  // [NT*8] 2-hop customer means
#define OFF_MMP   (OFF_MMC + (size_t)NT * 8)      // [NT*8] 2-hop product means
#define SCR_TOTAL (OFF_MMP + (size_t)NT * 8)

__device__ float g_scr[SCR_TOTAL];
__device__ unsigned g_bar;

// ---------------- weight-prep scratch ----------------
__device__ float g_m1[7][1024];
__device__ float g_r1[7][128];
__device__ float g_m2[5][1024];
__device__ float g_r2[5][128];
__device__ float g_G[400];
__device__ float g_g[50];

// ---------------- grid barrier (counting; g_bar zeroed by a memset node) ----------------
__device__ __forceinline__ void gbar(int phase) {
    __syncthreads();
    if (threadIdx.x == 0) {
        __threadfence();                       // release: make my writes visible
        atomicAdd(&g_bar, 1u);
        unsigned target = (unsigned)phase * (unsigned)NCTA;
        while (*(volatile unsigned*)&g_bar < target) { __nanosleep(64); }
        __threadfence();                       // acquire: see everyone's writes
    }
    __syncthreads();
}

// ---------------- atomics ----------------
__device__ __forceinline__ void red_add_v4(float* addr, float4 v) {
    asm volatile("red.global.add.v4.f32 [%0], {%1,%2,%3,%4};"
                 :: "l"(addr), "f"(v.x), "f"(v.y), "f"(v.z), "f"(v.w)
                 : "memory");
}
__device__ __forceinline__ void red_add_f(float* addr, float v) {
    asm volatile("red.global.add.f32 [%0], %1;" :: "l"(addr), "f"(v) : "memory");
}

// ---------------- prep stages as device functions ----------------
__device__ void prep1_block(int b, int col,
                            const float* __restrict__ Wc, const float* __restrict__ bc,
                            const float* __restrict__ Wn, const float* __restrict__ Wr,
                            const float* __restrict__ bl) {
    if (b < 7) {
        int X = 0; const float* M1 = Wn; const float* M2 = nullptr; float s = 1.f;
        switch (b) {
            case 0: X = 1; M1 = Wr;             M2 = Wr + 2 * 16384; s = 0.5f; break;
            case 1: X = 0; M1 = Wn;             s = 0.5f; break;
            case 2: X = 2; M1 = Wn + 2 * 16384; s = 0.5f; break;
            case 3: X = 0; M1 = Wr + 1 * 16384; break;
            case 4: X = 1; M1 = Wn + 1 * 16384; break;
            case 5: X = 2; M1 = Wr + 3 * 16384; break;
            case 6: X = 1; M1 = Wn + 3 * 16384; break;
        }
        #pragma unroll 2
        for (int f = 0; f < 8; f++) {
            float acc = 0.f;
            #pragma unroll 4
            for (int d = 0; d < 16; d++) {
                int k = f * 16 + d;
                float m = M1[k * 128 + col];
                if (M2) m += M2[k * 128 + col];
                acc += Wc[X * 128 + k] * m;
            }
            g_m1[b][f * 128 + col] = s * acc;
        }
    } else {
        int r = b - 7;
        float acc = 0.f;
        switch (r) {
            case 0:
                #pragma unroll 8
                for (int k = 0; k < 128; k++) acc += bc[k] * Wn[k * 128 + col];
                g_r1[0][col] = 0.5f * acc; break;
            case 1:
                #pragma unroll 8
                for (int k = 0; k < 128; k++) acc += bc[256 + k] * Wn[2 * 16384 + k * 128 + col];
                g_r1[1][col] = 0.5f * acc; break;
            case 2:
                #pragma unroll 8
                for (int k = 0; k < 128; k++)
                    acc += bc[128 + k] * (Wr[k * 128 + col] + Wr[2 * 16384 + k * 128 + col]);
                g_r1[2][col] = 0.5f * (acc + bl[0 * 128 + col] + bl[2 * 128 + col]); break;
            case 3:
                #pragma unroll 8
                for (int k = 0; k < 128; k++) acc += bc[128 + k] * Wn[1 * 16384 + k * 128 + col];
                g_r1[3][col] = acc; break;
            case 4:
                #pragma unroll 8
                for (int k = 0; k < 128; k++) acc += bc[k] * Wr[1 * 16384 + k * 128 + col];
                g_r1[4][col] = acc + bl[1 * 128 + col]; break;
            case 5:
                #pragma unroll 8
                for (int k = 0; k < 128; k++) acc += bc[128 + k] * Wn[3 * 16384 + k * 128 + col];
                g_r1[5][col] = acc; break;
            case 6:
                #pragma unroll 8
                for (int k = 0; k < 128; k++) acc += bc[256 + k] * Wr[3 * 16384 + k * 128 + col];
                g_r1[6][col] = acc + bl[3 * 128 + col]; break;
        }
    }
}

__device__ void prep2_block(int b, int col,
                            const float* __restrict__ Wn, const float* __restrict__ Wr,
                            const float* __restrict__ bl) {
    const float* Un = Wn + 4 * 16384;
    const float* Vn = Wn + 6 * 16384;
    const float* R0 = Wr + 4 * 16384;
    const float* R2 = Wr + 6 * 16384;
    if (b < 40) {
        int m = b >> 3, f = b & 7;
        float acc = 0.f;
        #pragma unroll 4
        for (int k = 0; k < 128; k++) {
            float w = 0.f;
            switch (m) {
                case 0: w = g_m1[0][f * 128 + k] * 0.5f * (R0[k * 128 + col] + R2[k * 128 + col]); break;
                case 1: w = g_m1[3][f * 128 + k] * 0.5f * Un[k * 128 + col]
                          + g_m1[1][f * 128 + k] * 0.5f * (R0[k * 128 + col] + R2[k * 128 + col]); break;
                case 2: w = g_m1[5][f * 128 + k] * 0.5f * Vn[k * 128 + col]
                          + g_m1[2][f * 128 + k] * 0.5f * (R0[k * 128 + col] + R2[k * 128 + col]); break;
                case 3: w = g_m1[4][f * 128 + k] * 0.5f * Un[k * 128 + col]; break;
                case 4: w = g_m1[6][f * 128 + k] * 0.5f * Vn[k * 128 + col]; break;
            }
            acc += w;
        }
        g_m2[m][f * 128 + col] = acc;
    } else {
        int r = b - 40;
        float acc = 0.f;
        #pragma unroll 4
        for (int k = 0; k < 128; k++) {
            float U = 0.5f * Un[k * 128 + col];
            float V = 0.5f * Vn[k * 128 + col];
            float R = 0.5f * (R0[k * 128 + col] + R2[k * 128 + col]);
            switch (r) {
                case 0: acc += g_r1[3][k] * U; break;
                case 1: acc += g_r1[5][k] * V; break;
                case 2: acc += g_r1[4][k] * U + g_r1[0][k] * R; break;
                case 3: acc += g_r1[6][k] * V + g_r1[1][k] * R; break;
                case 4: acc += g_r1[2][k] * R; break;
            }
        }
        if (r == 4) acc += 0.5f * (bl[4 * 128 + col] + bl[6 * 128 + col]);
        g_r2[r][col] = acc;
    }
}

// one warp per output entry (450 outputs): lane-strided dot over k=0..127
__device__ void prep3_warp(int w, int lane,
                           const float* __restrict__ Wout, const float* __restrict__ bout) {
    if (w < 400) {
        int m = w / 80, f = (w % 80) / 10, o = w % 10;
        float acc = 0.f;
        #pragma unroll
        for (int k = lane; k < 128; k += 32) acc += g_m2[m][f * 128 + k] * Wout[k * 10 + o];
        #pragma unroll
        for (int off = 16; off > 0; off >>= 1) acc += __shfl_xor_sync(0xffffffffu, acc, off);
        if (lane == 0) g_G[(m * 8 + f) * 10 + o] = acc;
    } else if (w < 450) {
        int r = (w - 400) / 10, o = (w - 400) % 10;
        float acc = 0.f;
        #pragma unroll
        for (int k = lane; k < 128; k += 32) acc += g_r2[r][k] * Wout[k * 10 + o];
        #pragma unroll
        for (int off = 16; off > 0; off >>= 1) acc += __shfl_xor_sync(0xffffffffu, acc, off);
        if (lane == 0) g_g[r * 10 + o] = acc + (r == 4 ? bout[o] : 0.f);
    }
}

// ---------------- the fused persistent kernel ----------------
__global__ __launch_bounds__(NTHR, 3)
void fused(const float* __restrict__ x_c, const float* __restrict__ x_t,
           const float* __restrict__ x_p,
           const float* __restrict__ W_col, const float* __restrict__ b_col,
           const float* __restrict__ Wn, const float* __restrict__ Wr,
           const float* __restrict__ b_lin,
           const float* __restrict__ W_out, const float* __restrict__ b_out,
           const int* __restrict__ em_src, const int* __restrict__ em_dst,
           const int* __restrict__ ei_src, const int* __restrict__ ei_dst,
           float* __restrict__ out) {
    const int tid = threadIdx.x;
    const int bid = blockIdx.x;
    float* scr = g_scr;

    // ---- P0: zero scratch ----
    {
        float4 z = make_float4(0.f, 0.f, 0.f, 0.f);
        float4* p = (float4*)scr;
        int n4 = (int)(SCR_TOTAL / 4);
        for (int i = bid * NTHR + tid; i < n4; i += NCTA * NTHR) p[i] = z;
    }
    gbar(1);

    // ---- P1: 1-hop scatters (both directions) ; CTAs 0..13 also run prep1 ----
    if (bid < 14 && tid < 128)
        prep1_block(bid, tid, W_col, b_col, Wn, Wr, b_lin);
    {
        const int W1 = NCTA - 14;
        for (int e0 = (bid - 14) * NTHR + tid; e0 >= 0 && e0 < ET; e0 += W1 * NTHR) {
            int e = e0;
            const int *src, *dst;
            const float* xs;
            float *aggd, *aggs, *cntd, *cnts;
            if (e < EM) {
                src = em_src; dst = em_dst; xs = x_c;
                aggd = scr + OFF_MTC; aggs = scr + OFF_MCS;
                cntd = scr + OFF_CMT; cnts = scr + OFF_CMC;
            } else {
                e -= EM;
                src = ei_src; dst = ei_dst; xs = x_p;
                aggd = scr + OFF_MTP; aggs = scr + OFF_MPS;
                cntd = scr + OFF_CIT; cnts = scr + OFF_CIP;
            }
            int s = __ldg(src + e);
            int d = __ldg(dst + e);
            const float4* ps = (const float4*)(xs + (size_t)s * 8);
            const float4* pd = (const float4*)(x_t + (size_t)d * 8);
            float4 a0 = ps[0], a1 = ps[1];
            float4 b0 = pd[0], b1 = pd[1];
            float* od = aggd + (size_t)d * 8;
            float* os = aggs + (size_t)s * 8;
            red_add_v4(od,     a0);  red_add_v4(od + 4, a1);
            red_add_v4(os,     b0);  red_add_v4(os + 4, b1);
            red_add_f(cntd + d, 1.0f);
            red_add_f(cnts + s, 1.0f);
        }
    }
    gbar(2);

    // ---- P2: 2-hop mean scatter ; CTAs 0..44 also run prep2 ----
    if (bid < 45 && tid < 128)
        prep2_block(bid, tid, Wn, Wr, b_lin);
    {
        const int W2 = NCTA - 45;
        for (int e0 = (bid - 45) * NTHR + tid; e0 >= 0 && e0 < ET; e0 += W2 * NTHR) {
            int e = e0;
            const int *src, *dst;
            const float *msum, *cnt;
            float* mm;
            if (e < EM) {
                src = em_src; dst = em_dst;
                msum = scr + OFF_MCS; cnt = scr + OFF_CMC; mm = scr + OFF_MMC;
            } else {
                e -= EM;
                src = ei_src; dst = ei_dst;
                msum = scr + OFF_MPS; cnt = scr + OFF_CIP; mm = scr + OFF_MMP;
            }
            int s = __ldg(src + e);
            int d = __ldg(dst + e);
            float c  = __ldg(cnt + s);
            float iv = 1.0f / fmaxf(c, 1.0f);
            const float4* pm = (const float4*)(msum + (size_t)s * 8);
            float4 v0 = pm[0], v1 = pm[1];
            v0.x *= iv; v0.y *= iv; v0.z *= iv; v0.w *= iv;
            v1.x *= iv; v1.y *= iv; v1.z *= iv; v1.w *= iv;
            float* o = mm + (size_t)d * 8;
            red_add_v4(o,     v0);
            red_add_v4(o + 4, v1);
        }
    }
    gbar(3);

    // ---- P3: prep3 (450 warp-dot products across CTAs 0..56) ----
    if (bid < 57) {
        int w = bid * (NTHR / 32) + (tid >> 5);
        prep3_warp(w, tid & 31, W_out, b_out);
    }
    gbar(4);

    // ---- P4: final linear model + softmax ----
    __shared__ float sG[400];
    __shared__ float sg[50];
    for (int i = tid; i < 400; i += NTHR) sG[i] = g_G[i];
    if (tid < 50) sg[tid] = g_g[tid];
    __syncthreads();

    for (int t = bid * NTHR + tid; t < NT; t += NCTA * NTHR) {
        float cm = scr[OFF_CMT + t], ci = scr[OFF_CIT + t];
        float im = 1.f / fmaxf(cm, 1.f);
        float ii = 1.f / fmaxf(ci, 1.f);
        float dm = cm > 0.f ? 1.f : 0.f;
        float di = ci > 0.f ? 1.f : 0.f;

        float feat[40];
        {
            const float4* p;
            float4 a, b;
            p = (const float4*)(x_t + (size_t)t * 8); a = p[0]; b = p[1];
            feat[0]=a.x; feat[1]=a.y; feat[2]=a.z; feat[3]=a.w;
            feat[4]=b.x; feat[5]=b.y; feat[6]=b.z; feat[7]=b.w;
            p = (const float4*)(scr + OFF_MTC + (size_t)t * 8); a = p[0]; b = p[1];
            feat[8]=a.x*im; feat[9]=a.y*im; feat[10]=a.z*im; feat[11]=a.w*im;
            feat[12]=b.x*im; feat[13]=b.y*im; feat[14]=b.z*im; feat[15]=b.w*im;
            p = (const float4*)(scr + OFF_MTP + (size_t)t * 8); a = p[0]; b = p[1];
            feat[16]=a.x*ii; feat[17]=a.y*ii; feat[18]=a.z*ii; feat[19]=a.w*ii;
            feat[20]=b.x*ii; feat[21]=b.y*ii; feat[22]=b.z*ii; feat[23]=b.w*ii;
            p = (const float4*)(scr + OFF_MMC + (size_t)t * 8); a = p[0]; b = p[1];
            feat[24]=a.x*im; feat[25]=a.y*im; feat[26]=a.z*im; feat[27]=a.w*im;
            feat[28]=b.x*im; feat[29]=b.y*im; feat[30]=b.z*im; feat[31]=b.w*im;
            p = (const float4*)(scr + OFF_MMP + (size_t)t * 8); a = p[0]; b = p[1];
            feat[32]=a.x*ii; feat[33]=a.y*ii; feat[34]=a.z*ii; feat[35]=a.w*ii;
            feat[36]=b.x*ii; feat[37]=b.y*ii; feat[38]=b.z*ii; feat[39]=b.w*ii;
        }

        float p[NOUT];
        #pragma unroll
        for (int o = 0; o < NOUT; o++) {
            float s = sg[40 + o];
            s = fmaf(dm, sg[o]      + sg[20 + o], s);
            s = fmaf(di, sg[10 + o] + sg[30 + o], s);
            p[o] = s;
        }
        #pragma unroll
        for (int f = 0; f < 40; f++) {
            float xv = feat[f];
            #pragma unroll
            for (int o = 0; o < NOUT; o++) p[o] = fmaf(xv, sG[f * 10 + o], p[o]);
        }

        float m = p[0];
        #pragma unroll
        for (int o = 1; o < NOUT; o++) m = fmaxf(m, p[o]);
        float sum = 0.f;
        #pragma unroll
        for (int o = 0; o < NOUT; o++) { p[o] = expf(p[o] - m); sum += p[o]; }
        float isum = 1.0f / sum;
        #pragma unroll
        for (int o = 0; o < NOUT; o++) out[(size_t)t * NOUT + o] = p[o] * isum;
    }
}

// ---------------- host orchestration ----------------
extern "C" void kernel_launch(void* const* d_in, const int* in_sizes, int n_in,
                              void* d_out, int out_size) {
    const float* x_c   = (const float*)d_in[0];
    const float* x_t   = (const float*)d_in[1];
    const float* x_p   = (const float*)d_in[2];
    const float* W_col = (const float*)d_in[3];
    const float* b_col = (const float*)d_in[4];
    const float* Wn    = (const float*)d_in[5];
    const float* Wr    = (const float*)d_in[6];
    const float* b_lin = (const float*)d_in[7];
    const float* W_out = (const float*)d_in[8];
    const float* b_out = (const float*)d_in[9];
    const int* em_src  = (const int*)d_in[10];
    const int* em_dst  = (const int*)d_in[11];
    const int* ei_src  = (const int*)d_in[12];
    const int* ei_dst  = (const int*)d_in[13];
    float* out = (float*)d_out;

    // reset barrier counter (graph-capturable memset node)
    unsigned* bar_addr;
    cudaGetSymbolAddress((void**)&bar_addr, g_bar);
    cudaMemsetAsync(bar_addr, 0, sizeof(unsigned));

    fused<<<NCTA, NTHR>>>(x_c, x_t, x_p, W_col, b_col, Wn, Wr, b_lin,
                          W_out, b_out, em_src, em_dst, ei_src, ei_dst, out);
}

// round 12
// speedup vs baseline: 2.1246x; 2.1246x over previous
#include <cuda_runtime.h>

// ---------------- problem sizes ----------------
#define NC 100000
#define NT 300000
#define NP 50000
#define EM 300000
#define EI 600000
#define ET (EM + EI)
#define NOUT 10

#define NCTA 888          // 6 CTAs/SM on 148 SMs (GB300 has 152 -> co-residency guaranteed)
#define NTHR 256

// ---------------- scratch layout ----------------
#define OFF_MCS   0                               // [NC*8] sum x_t over c's transactions
#define OFF_MPS   (OFF_MCS + (size_t)NC * 8)      // [NP*8] sum x_t over p's transactions
#define OFF_CMC   (OFF_MPS + (size_t)NP * 8)      // [NC] deg(c)
#define OFF_CIP   (OFF_CMC + NC)                  // [NP] deg(p)
#define OFF_MTC   (OFF_CIP + NP)                  // [NT*8] sum x_c over t's customers
#define OFF_MTP   (OFF_MTC + (size_t)NT * 8)      // [NT*8] sum x_p over t's products
#define OFF_CMT   (OFF_MTP + (size_t)NT * 8)      // [NT] deg(t, makes)
#define OFF_CIT   (OFF_CMT + NT)                  // [NT] deg(t, in)
#define OFF_MMC   (OFF_CIT + NT)                  // [NT*8] 2-hop customer sums
#define OFF_MMP   (OFF_MMC + (size_t)NT * 8)      // [NT*8] 2-hop product sums
#define SCR_TOTAL (OFF_MMP + (size_t)NT * 8)

__device__ float g_scr[SCR_TOTAL];
__device__ unsigned g_bar;

// ---------------- weight-prep scratch ----------------
__device__ float g_m1[7][1024];
__device__ float g_r1[7][128];
__device__ float g_m2[5][1024];
__device__ float g_r2[5][128];
__device__ float g_G[400];
__device__ float g_g[50];

// ---------------- grid barrier ----------------
__device__ __forceinline__ void gbar(int phase) {
    __syncthreads();
    if (threadIdx.x == 0) {
        __threadfence();
        atomicAdd(&g_bar, 1u);
        unsigned target = (unsigned)phase * (unsigned)NCTA;
        while (*(volatile unsigned*)&g_bar < target) { __nanosleep(64); }
        __threadfence();
    }
    __syncthreads();
}

// ---------------- atomics ----------------
__device__ __forceinline__ void red_add_v4(float* addr, float4 v) {
    asm volatile("red.global.add.v4.f32 [%0], {%1,%2,%3,%4};"
                 :: "l"(addr), "f"(v.x), "f"(v.y), "f"(v.z), "f"(v.w)
                 : "memory");
}
__device__ __forceinline__ void red_add_f(float* addr, float v) {
    asm volatile("red.global.add.f32 [%0], %1;" :: "l"(addr), "f"(v) : "memory");
}

// ---------------- prep stages ----------------
__device__ void prep1_block(int b, int col,
                            const float* __restrict__ Wc, const float* __restrict__ bc,
                            const float* __restrict__ Wn, const float* __restrict__ Wr,
                            const float* __restrict__ bl) {
    if (b < 7) {
        int X = 0; const float* M1 = Wn; const float* M2 = nullptr; float s = 1.f;
        switch (b) {
            case 0: X = 1; M1 = Wr;             M2 = Wr + 2 * 16384; s = 0.5f; break;
            case 1: X = 0; M1 = Wn;             s = 0.5f; break;
            case 2: X = 2; M1 = Wn + 2 * 16384; s = 0.5f; break;
            case 3: X = 0; M1 = Wr + 1 * 16384; break;
            case 4: X = 1; M1 = Wn + 1 * 16384; break;
            case 5: X = 2; M1 = Wr + 3 * 16384; break;
            case 6: X = 1; M1 = Wn + 3 * 16384; break;
        }
        for (int f = 0; f < 8; f++) {
            float acc = 0.f;
            #pragma unroll 4
            for (int d = 0; d < 16; d++) {
                int k = f * 16 + d;
                float m = M1[k * 128 + col];
                if (M2) m += M2[k * 128 + col];
                acc += Wc[X * 128 + k] * m;
            }
            g_m1[b][f * 128 + col] = s * acc;
        }
    } else {
        int r = b - 7;
        float acc = 0.f;
        switch (r) {
            case 0:
                for (int k = 0; k < 128; k++) acc += bc[k] * Wn[k * 128 + col];
                g_r1[0][col] = 0.5f * acc; break;
            case 1:
                for (int k = 0; k < 128; k++) acc += bc[256 + k] * Wn[2 * 16384 + k * 128 + col];
                g_r1[1][col] = 0.5f * acc; break;
            case 2:
                for (int k = 0; k < 128; k++)
                    acc += bc[128 + k] * (Wr[k * 128 + col] + Wr[2 * 16384 + k * 128 + col]);
                g_r1[2][col] = 0.5f * (acc + bl[0 * 128 + col] + bl[2 * 128 + col]); break;
            case 3:
                for (int k = 0; k < 128; k++) acc += bc[128 + k] * Wn[1 * 16384 + k * 128 + col];
                g_r1[3][col] = acc; break;
            case 4:
                for (int k = 0; k < 128; k++) acc += bc[k] * Wr[1 * 16384 + k * 128 + col];
                g_r1[4][col] = acc + bl[1 * 128 + col]; break;
            case 5:
                for (int k = 0; k < 128; k++) acc += bc[128 + k] * Wn[3 * 16384 + k * 128 + col];
                g_r1[5][col] = acc; break;
            case 6:
                for (int k = 0; k < 128; k++) acc += bc[256 + k] * Wr[3 * 16384 + k * 128 + col];
                g_r1[6][col] = acc + bl[3 * 128 + col]; break;
        }
    }
}

__device__ void prep2_block(int b, int col,
                            const float* __restrict__ Wn, const float* __restrict__ Wr,
                            const float* __restrict__ bl) {
    const float* Un = Wn + 4 * 16384;
    const float* Vn = Wn + 6 * 16384;
    const float* R0 = Wr + 4 * 16384;
    const float* R2 = Wr + 6 * 16384;
    if (b < 40) {
        int m = b >> 3, f = b & 7;
        float acc = 0.f;
        #pragma unroll 4
        for (int k = 0; k < 128; k++) {
            float w = 0.f;
            switch (m) {
                case 0: w = g_m1[0][f * 128 + k] * 0.5f * (R0[k * 128 + col] + R2[k * 128 + col]); break;
                case 1: w = g_m1[3][f * 128 + k] * 0.5f * Un[k * 128 + col]
                          + g_m1[1][f * 128 + k] * 0.5f * (R0[k * 128 + col] + R2[k * 128 + col]); break;
                case 2: w = g_m1[5][f * 128 + k] * 0.5f * Vn[k * 128 + col]
                          + g_m1[2][f * 128 + k] * 0.5f * (R0[k * 128 + col] + R2[k * 128 + col]); break;
                case 3: w = g_m1[4][f * 128 + k] * 0.5f * Un[k * 128 + col]; break;
                case 4: w = g_m1[6][f * 128 + k] * 0.5f * Vn[k * 128 + col]; break;
            }
            acc += w;
        }
        g_m2[m][f * 128 + col] = acc;
    } else {
        int r = b - 40;
        float acc = 0.f;
        #pragma unroll 4
        for (int k = 0; k < 128; k++) {
            float U = 0.5f * Un[k * 128 + col];
            float V = 0.5f * Vn[k * 128 + col];
            float R = 0.5f * (R0[k * 128 + col] + R2[k * 128 + col]);
            switch (r) {
                case 0: acc += g_r1[3][k] * U; break;
                case 1: acc += g_r1[5][k] * V; break;
                case 2: acc += g_r1[4][k] * U + g_r1[0][k] * R; break;
                case 3: acc += g_r1[6][k] * V + g_r1[1][k] * R; break;
                case 4: acc += g_r1[2][k] * R; break;
            }
        }
        if (r == 4) acc += 0.5f * (bl[4 * 128 + col] + bl[6 * 128 + col]);
        g_r2[r][col] = acc;
    }
}

__device__ void prep3_warp(int w, int lane,
                           const float* __restrict__ Wout, const float* __restrict__ bout) {
    if (w < 400) {
        int m = w / 80, f = (w % 80) / 10, o = w % 10;
        float acc = 0.f;
        #pragma unroll
        for (int k = lane; k < 128; k += 32) acc += g_m2[m][f * 128 + k] * Wout[k * 10 + o];
        #pragma unroll
        for (int off = 16; off > 0; off >>= 1) acc += __shfl_xor_sync(0xffffffffu, acc, off);
        if (lane == 0) g_G[(m * 8 + f) * 10 + o] = acc;
    } else if (w < 450) {
        int r = (w - 400) / 10, o = (w - 400) % 10;
        float acc = 0.f;
        #pragma unroll
        for (int k = lane; k < 128; k += 32) acc += g_r2[r][k] * Wout[k * 10 + o];
        #pragma unroll
        for (int off = 16; off > 0; off >>= 1) acc += __shfl_xor_sync(0xffffffffu, acc, off);
        if (lane == 0) g_g[r * 10 + o] = acc + (r == 4 ? bout[o] : 0.f);
    }
}

// ---------------- persistent kernel: P0 zero, P1 edges+prep1, P2 edges+prep2, P3 prep3 ----------------
__global__ __launch_bounds__(NTHR, 6)
void fused(const float* __restrict__ x_c, const float* __restrict__ x_t,
           const float* __restrict__ x_p,
           const float* __restrict__ W_col, const float* __restrict__ b_col,
           const float* __restrict__ Wn, const float* __restrict__ Wr,
           const float* __restrict__ b_lin,
           const float* __restrict__ W_out, const float* __restrict__ b_out,
           const int* __restrict__ em_src, const int* __restrict__ em_dst,
           const int* __restrict__ ei_src, const int* __restrict__ ei_dst) {
    const int tid = threadIdx.x;
    const int bid = blockIdx.x;
    float* scr = g_scr;

    // ---- P0: zero scratch ----
    {
        float4 z = make_float4(0.f, 0.f, 0.f, 0.f);
        float4* p = (float4*)scr;
        int n4 = (int)(SCR_TOTAL / 4);
        for (int i = bid * NTHR + tid; i < n4; i += NCTA * NTHR) p[i] = z;
    }
    gbar(1);

    // ---- P1: 1-hop scatters ; CTAs 0..13 run prep1 instead ----
    if (bid < 14) {
        if (tid < 128) prep1_block(bid, tid, W_col, b_col, Wn, Wr, b_lin);
    }
    {
        const int W1 = NCTA - 14;
        for (int e0 = (bid - 14) * NTHR + tid; e0 >= 0 && e0 < ET; e0 += W1 * NTHR) {
            int e = e0;
            const int *src, *dst;
            const float* xs;
            float *aggd, *aggs, *cntd, *cnts;
            if (e < EM) {
                src = em_src; dst = em_dst; xs = x_c;
                aggd = scr + OFF_MTC; aggs = scr + OFF_MCS;
                cntd = scr + OFF_CMT; cnts = scr + OFF_CMC;
            } else {
                e -= EM;
                src = ei_src; dst = ei_dst; xs = x_p;
                aggd = scr + OFF_MTP; aggs = scr + OFF_MPS;
                cntd = scr + OFF_CIT; cnts = scr + OFF_CIP;
            }
            int s = __ldg(src + e);
            int d = __ldg(dst + e);
            const float4* ps = (const float4*)(xs + (size_t)s * 8);
            const float4* pd = (const float4*)(x_t + (size_t)d * 8);
            float4 a0 = ps[0], a1 = ps[1];
            float4 b0 = pd[0], b1 = pd[1];
            float* od = aggd + (size_t)d * 8;
            float* os = aggs + (size_t)s * 8;
            red_add_v4(od,     a0);  red_add_v4(od + 4, a1);
            red_add_v4(os,     b0);  red_add_v4(os + 4, b1);
            red_add_f(cntd + d, 1.0f);
            red_add_f(cnts + s, 1.0f);
        }
    }
    gbar(2);

    // ---- P2: 2-hop mean scatter ; CTAs 0..44 run prep2 instead ----
    if (bid < 45) {
        if (tid < 128) prep2_block(bid, tid, Wn, Wr, b_lin);
    }
    {
        const int W2 = NCTA - 45;
        for (int e0 = (bid - 45) * NTHR + tid; e0 >= 0 && e0 < ET; e0 += W2 * NTHR) {
            int e = e0;
            const int *src, *dst;
            const float *msum, *cnt;
            float* mm;
            if (e < EM) {
                src = em_src; dst = em_dst;
                msum = scr + OFF_MCS; cnt = scr + OFF_CMC; mm = scr + OFF_MMC;
            } else {
                e -= EM;
                src = ei_src; dst = ei_dst;
                msum = scr + OFF_MPS; cnt = scr + OFF_CIP; mm = scr + OFF_MMP;
            }
            int s = __ldg(src + e);
            int d = __ldg(dst + e);
            float c  = __ldg(cnt + s);
            float iv = 1.0f / fmaxf(c, 1.0f);
            const float4* pm = (const float4*)(msum + (size_t)s * 8);
            float4 v0 = pm[0], v1 = pm[1];
            v0.x *= iv; v0.y *= iv; v0.z *= iv; v0.w *= iv;
            v1.x *= iv; v1.y *= iv; v1.z *= iv; v1.w *= iv;
            float* o = mm + (size_t)d * 8;
            red_add_v4(o,     v0);
            red_add_v4(o + 4, v1);
        }
    }
    gbar(3);

    // ---- P3: prep3 (450 warp-dots; kernel boundary orders this before final) ----
    if (bid < 57) {
        int w = bid * (NTHR / 32) + (tid >> 5);
        prep3_warp(w, tid & 31, W_out, b_out);
    }
}

// ---------------- final: 40-feature linear model + degree gates + softmax ----------------
__global__ __launch_bounds__(256)
void final_kernel(const float* __restrict__ xt, float* __restrict__ out) {
    __shared__ float sG[400];
    __shared__ float sg[50];
    int tid = threadIdx.x;
    for (int i = tid; i < 400; i += 256) sG[i] = g_G[i];
    if (tid < 50) sg[tid] = g_g[tid];
    __syncthreads();

    int t = blockIdx.x * 256 + tid;
    if (t >= NT) return;

    float cm = g_scr[OFF_CMT + t], ci = g_scr[OFF_CIT + t];
    float im = 1.f / fmaxf(cm, 1.f);
    float ii = 1.f / fmaxf(ci, 1.f);
    float dm = cm > 0.f ? 1.f : 0.f;
    float di = ci > 0.f ? 1.f : 0.f;

    float feat[40];
    {
        const float4* p;
        float4 a, b;
        p = (const float4*)(xt + (size_t)t * 8); a = p[0]; b = p[1];
        feat[0]=a.x; feat[1]=a.y; feat[2]=a.z; feat[3]=a.w;
        feat[4]=b.x; feat[5]=b.y; feat[6]=b.z; feat[7]=b.w;
        p = (const float4*)(g_scr + OFF_MTC + (size_t)t * 8); a = p[0]; b = p[1];
        feat[8]=a.x*im; feat[9]=a.y*im; feat[10]=a.z*im; feat[11]=a.w*im;
        feat[12]=b.x*im; feat[13]=b.y*im; feat[14]=b.z*im; feat[15]=b.w*im;
        p = (const float4*)(g_scr + OFF_MTP + (size_t)t * 8); a = p[0]; b = p[1];
        feat[16]=a.x*ii; feat[17]=a.y*ii; feat[18]=a.z*ii; feat[19]=a.w*ii;
        feat[20]=b.x*ii; feat[21]=b.y*ii; feat[22]=b.z*ii; feat[23]=b.w*ii;
        p = (const float4*)(g_scr + OFF_MMC + (size_t)t * 8); a = p[0]; b = p[1];
        feat[24]=a.x*im; feat[25]=a.y*im; feat[26]=a.z*im; feat[27]=a.w*im;
        feat[28]=b.x*im; feat[29]=b.y*im; feat[30]=b.z*im; feat[31]=b.w*im;
        p = (const float4*)(g_scr + OFF_MMP + (size_t)t * 8); a = p[0]; b = p[1];
        feat[32]=a.x*ii; feat[33]=a.y*ii; feat[34]=a.z*ii; feat[35]=a.w*ii;
        feat[36]=b.x*ii; feat[37]=b.y*ii; feat[38]=b.z*ii; feat[39]=b.w*ii;
    }

    float p[NOUT];
    #pragma unroll
    for (int o = 0; o < NOUT; o++) {
        float s = sg[40 + o];
        s = fmaf(dm, sg[o]      + sg[20 + o], s);
        s = fmaf(di, sg[10 + o] + sg[30 + o], s);
        p[o] = s;
    }
    #pragma unroll
    for (int f = 0; f < 40; f++) {
        float xv = feat[f];
        #pragma unroll
        for (int o = 0; o < NOUT; o++) p[o] = fmaf(xv, sG[f * 10 + o], p[o]);
    }

    float m = p[0];
    #pragma unroll
    for (int o = 1; o < NOUT; o++) m = fmaxf(m, p[o]);
    float sum = 0.f;
    #pragma unroll
    for (int o = 0; o < NOUT; o++) { p[o] = expf(p[o] - m); sum += p[o]; }
    float isum = 1.0f / sum;
    #pragma unroll
    for (int o = 0; o < NOUT; o++) out[(size_t)t * NOUT + o] = p[o] * isum;
}

// ---------------- host orchestration ----------------
extern "C" void kernel_launch(void* const* d_in, const int* in_sizes, int n_in,
                              void* d_out, int out_size) {
    const float* x_c   = (const float*)d_in[0];
    const float* x_t   = (const float*)d_in[1];
    const float* x_p   = (const float*)d_in[2];
    const float* W_col = (const float*)d_in[3];
    const float* b_col = (const float*)d_in[4];
    const float* Wn    = (const float*)d_in[5];
    const float* Wr    = (const float*)d_in[6];
    const float* b_lin = (const float*)d_in[7];
    const float* W_out = (const float*)d_in[8];
    const float* b_out = (const float*)d_in[9];
    const int* em_src  = (const int*)d_in[10];
    const int* em_dst  = (const int*)d_in[11];
    const int* ei_src  = (const int*)d_in[12];
    const int* ei_dst  = (const int*)d_in[13];
    float* out = (float*)d_out;

    unsigned* bar_addr;
    cudaGetSymbolAddress((void**)&bar_addr, g_bar);
    cudaMemsetAsync(bar_addr, 0, sizeof(unsigned));

    fused<<<NCTA, NTHR>>>(x_c, x_t, x_p, W_col, b_col, Wn, Wr, b_lin,
                          W_out, b_out, em_src, em_dst, ei_src, ei_dst);
    final_kernel<<<(NT + 255) / 256, 256>>>(x_t, out);
}